// round 5
// baseline (speedup 1.0000x reference)
#include <cuda_runtime.h>
#include <cuda_bf16.h>
#include <cstdint>

// Embedding gather: out[i, :] = table[indices[i], :]
// indices: int32 [819200], table: fp32 [1M, 64], out: fp32 [819200, 64].
// 16 lanes per row (one float4 each). Unroll 4 rows per thread (quarters of
// the row space) to get 4 independent in-flight table loads per thread.
// Streaming stores (__stcs) keep L2 reserved for table rows (~32% dup hits).

__global__ void __launch_bounds__(256)
emb_gather_u4_kernel(const int* __restrict__ idx,
                     const float4* __restrict__ table,
                     float4* __restrict__ out,
                     int nrows, int quarter) {
    int t = blockIdx.x * blockDim.x + threadIdx.x;
    int row = t >> 4;          // row within first quarter
    int lane = t & 15;
    if (row >= quarter) return;

    int r0 = row;
    int r1 = row + quarter;
    int r2 = row + 2 * quarter;
    int r3 = row + 3 * quarter;

    // Batch independent index loads (coalesced, L1/L2 friendly)
    int i0 = __ldg(&idx[r0]);
    int i1 = __ldg(&idx[r1]);
    int i2 = (r2 < nrows) ? __ldg(&idx[r2]) : 0;
    int i3 = (r3 < nrows) ? __ldg(&idx[r3]) : 0;

    // Batch independent random table loads: MLP = 4
    float4 v0 = __ldg(&table[(size_t)i0 * 16 + lane]);
    float4 v1 = __ldg(&table[(size_t)i1 * 16 + lane]);
    float4 v2 = __ldg(&table[(size_t)i2 * 16 + lane]);
    float4 v3 = __ldg(&table[(size_t)i3 * 16 + lane]);

    // Streaming stores — output is write-once, don't pollute L2
    __stcs(&out[(size_t)r0 * 16 + lane], v0);
    __stcs(&out[(size_t)r1 * 16 + lane], v1);
    if (r2 < nrows) __stcs(&out[(size_t)r2 * 16 + lane], v2);
    if (r3 < nrows) __stcs(&out[(size_t)r3 * 16 + lane], v3);
}

extern "C" void kernel_launch(void* const* d_in, const int* in_sizes, int n_in,
                              void* d_out, int out_size) {
    // Identify inputs by element count so ordering can't break us.
    const void* p_idx = d_in[0];
    const void* p_tab = d_in[1];
    int n_idx = in_sizes[0];
    if (n_in >= 2 && in_sizes[0] > in_sizes[1]) {
        p_tab = d_in[0];
        p_idx = d_in[1];
        n_idx = in_sizes[1];
    }

    const int*    idx = (const int*)p_idx;      // indices, int32, 819200 elems
    const float4* tab = (const float4*)p_tab;   // table, fp32, 64M elems
    float4*       out = (float4*)d_out;

    int nrows = n_idx;                          // 819200
    int quarter = (nrows + 3) / 4;              // rows handled per unroll slot
    long long total_threads = (long long)quarter * 16;
    int block = 256;
    int grid = (int)((total_threads + block - 1) / block);

    emb_gather_u4_kernel<<<grid, block>>>(idx, tab, out, nrows, quarter);
}

// round 6
// speedup vs baseline: 1.0065x; 1.0065x over previous
#include <cuda_runtime.h>
#include <cuda_bf16.h>
#include <cstdint>

// Embedding gather: out[i, :] = table[indices[i], :]
// indices: int32 [819200], table: fp32 [1M, 64], out: fp32 [819200, 64].
// 16 lanes per row (one float4 each). Unroll 4 rows per thread (quarters of
// the row space) to get 4 independent in-flight table loads per thread.
// Streaming stores (__stcs) keep L2 reserved for table rows (~32% dup hits).

__global__ void __launch_bounds__(256)
emb_gather_u4_kernel(const int* __restrict__ idx,
                     const float4* __restrict__ table,
                     float4* __restrict__ out,
                     int nrows, int quarter) {
    int t = blockIdx.x * blockDim.x + threadIdx.x;
    int row = t >> 4;          // row within first quarter
    int lane = t & 15;
    if (row >= quarter) return;

    int r0 = row;
    int r1 = row + quarter;
    int r2 = row + 2 * quarter;
    int r3 = row + 3 * quarter;

    // Batch independent index loads (coalesced, L1/L2 friendly)
    int i0 = __ldg(&idx[r0]);
    int i1 = __ldg(&idx[r1]);
    int i2 = (r2 < nrows) ? __ldg(&idx[r2]) : 0;
    int i3 = (r3 < nrows) ? __ldg(&idx[r3]) : 0;

    // Batch independent random table loads: MLP = 4
    float4 v0 = __ldg(&table[(size_t)i0 * 16 + lane]);
    float4 v1 = __ldg(&table[(size_t)i1 * 16 + lane]);
    float4 v2 = __ldg(&table[(size_t)i2 * 16 + lane]);
    float4 v3 = __ldg(&table[(size_t)i3 * 16 + lane]);

    // Streaming stores — output is write-once, don't pollute L2
    __stcs(&out[(size_t)r0 * 16 + lane], v0);
    __stcs(&out[(size_t)r1 * 16 + lane], v1);
    if (r2 < nrows) __stcs(&out[(size_t)r2 * 16 + lane], v2);
    if (r3 < nrows) __stcs(&out[(size_t)r3 * 16 + lane], v3);
}

extern "C" void kernel_launch(void* const* d_in, const int* in_sizes, int n_in,
                              void* d_out, int out_size) {
    // Identify inputs by element count so ordering can't break us.
    const void* p_idx = d_in[0];
    const void* p_tab = d_in[1];
    int n_idx = in_sizes[0];
    if (n_in >= 2 && in_sizes[0] > in_sizes[1]) {
        p_tab = d_in[0];
        p_idx = d_in[1];
        n_idx = in_sizes[1];
    }

    const int*    idx = (const int*)p_idx;      // indices, int32, 819200 elems
    const float4* tab = (const float4*)p_tab;   // table, fp32, 64M elems
    float4*       out = (float4*)d_out;

    int nrows = n_idx;                          // 819200
    int quarter = (nrows + 3) / 4;              // rows handled per unroll slot
    long long total_threads = (long long)quarter * 16;
    int block = 256;
    int grid = (int)((total_threads + block - 1) / block);

    emb_gather_u4_kernel<<<grid, block>>>(idx, tab, out, nrows, quarter);
}